// round 12
// baseline (speedup 1.0000x reference)
#include <cuda_runtime.h>
#include <cuda_fp16.h>
#include <cstdint>

// ---------------- problem constants ----------------
#define NT   1024          // T*B tokens
#define D_   512
#define L_   2
#define P_   17            // MULTI_INFER_NUM + 1

// ---------------- tiling ----------------
#define BM        48       // tokens per m-tile (3 x m16)
#define BN        64       // output cols per gate per CTA (x4 gates = 256 N)
#define KC        32       // k chunk per stage
#define NCH       (D_/KC)  // 16 chunks
#define MAX_TILES 40       // sum ceil(cnt_p/48) <= 17 + 21 = 38
#define NTH       256      // 8 warps

// smem byte strides (padded, conflict-free ldmatrix without XOR swizzle)
#define A_STRIDE  80       // 32 halfs (64B) padded to 80B per m-row
#define B_STRIDE  528      // 256 halfs (512B) padded to 528B per k-row
#define ASZ       (BM * A_STRIDE)     // 3840
#define BSZ       (KC * B_STRIDE)     // 16896

// dynamic smem layout
#define SM_TOKS   0                   // 48 * 4 = 192
#define SM_BIAS   192                 // 4*64*4 = 1024 -> ends 1216
#define SM_CNT    1216                // 17 * 4 = 68  -> ends 1284
#define SM_STAGE  1536                // stage buffers / epilogue / build-scratch union
#define OFF_A0    (SM_STAGE)
#define OFF_A1    (SM_STAGE + ASZ)
#define OFF_B0    (SM_STAGE + 2*ASZ)
#define OFF_B1    (SM_STAGE + 2*ASZ + BSZ)
#define EPI_STRIDE 65                 // fp32 cols incl. pad
#define EPI_BYTES (4 * BM * EPI_STRIDE * 4)        // 49920
#define SMEM_TOTAL (SM_STAGE + EPI_BYTES)          // 51456 (> stage end 43008)

// ---------------- device scratch ----------------
__device__ float g_mid[NT * D_];     // layer-0 output ping buffer (2 MB)

// ---------------- helpers ----------------
__device__ __forceinline__ uint32_t pk2(float a, float b) {
    __half2 h = __floats2half2_rn(a, b);
    return *reinterpret_cast<uint32_t*>(&h);
}
__device__ __forceinline__ uint32_t smem_u32(const void* p) {
    uint32_t a;
    asm("{ .reg .u64 t; cvta.to.shared.u64 t, %1; cvt.u32.u64 %0, t; }" : "=r"(a) : "l"(p));
    return a;
}
__device__ __forceinline__ void ldsm_x4(uint32_t* r, uint32_t addr) {
    asm volatile("ldmatrix.sync.aligned.m8n8.x4.shared.b16 {%0,%1,%2,%3}, [%4];"
                 : "=r"(r[0]), "=r"(r[1]), "=r"(r[2]), "=r"(r[3]) : "r"(addr));
}
__device__ __forceinline__ void ldsm_x4_t(uint32_t* r, uint32_t addr) {
    asm volatile("ldmatrix.sync.aligned.m8n8.x4.trans.shared.b16 {%0,%1,%2,%3}, [%4];"
                 : "=r"(r[0]), "=r"(r[1]), "=r"(r[2]), "=r"(r[3]) : "r"(addr));
}
__device__ __forceinline__ void mma16816(float* c, const uint32_t* a, uint32_t b0, uint32_t b1) {
    asm volatile(
        "mma.sync.aligned.m16n8k16.row.col.f32.f16.f16.f32 "
        "{%0,%1,%2,%3}, {%4,%5,%6,%7}, {%8,%9}, {%0,%1,%2,%3};"
        : "+f"(c[0]), "+f"(c[1]), "+f"(c[2]), "+f"(c[3])
        : "r"(a[0]), "r"(a[1]), "r"(a[2]), "r"(a[3]), "r"(b0), "r"(b1));
}
__device__ __forceinline__ float sigm_f(float v) { return 1.f / (1.f + __expf(-v)); }
__device__ __forceinline__ float tanh_f(float v) { return 2.f / (1.f + __expf(-2.f * v)) - 1.f; }

// ---------------- fused per-layer HMMA GEMM + gating (deterministic inline build) ----------------
__global__ void __launch_bounds__(NTH, 2)
layer_kernel(const int* __restrict__ positions,
             const float* __restrict__ x_ext_in,
             float* __restrict__ x_ext_out,
             const float* __restrict__ Ws_l,   // [4][P][D][D] fp32 for this layer
             const float* __restrict__ bs_l,   // [4][P][D]
             int in_is_mid, int out_is_mid)
{
    extern __shared__ __align__(16) char dsm[];
    int*   toks    = reinterpret_cast<int*>(dsm + SM_TOKS);
    float* bias_sm = reinterpret_cast<float*>(dsm + SM_BIAS);
    int*   cnt     = reinterpret_cast<int*>(dsm + SM_CNT);

    const float* x_in  = in_is_mid  ? g_mid : x_ext_in;
    float*       x_out = out_is_mid ? g_mid : x_ext_out;

    const int tile = blockIdx.x;
    const int n0   = blockIdx.y * BN;
    const int tid  = threadIdx.x;
    const int wid  = tid >> 5;
    const int lane = tid & 31;

    // ---- deterministic inline bucket build (identical result in EVERY CTA) ----
    // Tokens in fixed order as 32 lane-groups: group G = i*8 + wid, token t = G*32 + lane.
    // rank(t) = (count of same-bucket tokens in groups < G) + (same-bucket lanes < lane in G).
    // Scratch tables live in the (currently dead) stage region.
    {
        int* grpcnt = reinterpret_cast<int*>(dsm + SM_STAGE);          // [32][17]
        int* pre    = grpcnt + 32 * P_;                                // [32][17]

        for (int i = tid; i < 32 * P_; i += NTH) grpcnt[i] = 0;
        __syncthreads();

        int rr[4], rkg[4];
#pragma unroll
        for (int i = 0; i < 4; i++) {
            int G = i * 8 + wid;
            int t = G * 32 + lane;
            int r = positions[t];
            r = (r < 16) ? r : 16;
            unsigned mask   = __match_any_sync(0xffffffffu, r);
            unsigned before = mask & ((1u << lane) - 1u);
            rr[i]  = r;
            rkg[i] = __popc(before);
            if (before == 0) grpcnt[G * P_ + r] = __popc(mask);   // leader writes
        }
        __syncthreads();

        if (tid < P_) {          // serial per-bin scan over 32 groups (deterministic)
            int running = 0;
            for (int G = 0; G < 32; G++) {
                pre[G * P_ + tid] = running;
                running += grpcnt[G * P_ + tid];
            }
            cnt[tid] = running;
        }
        __syncthreads();

        // decode this CTA's tile (uniform across threads)
        int p = 0, lrow0 = 0, nrows = 0, acc = 0;
        bool live = false;
#pragma unroll 1
        for (int q = 0; q < P_; q++) {
            int c   = cnt[q];
            int ntl = (c + BM - 1) / BM;
            if (!live && tile < acc + ntl) {
                p     = q;
                lrow0 = (tile - acc) * BM;
                nrows = c - lrow0;
                if (nrows > BM) nrows = BM;
                live  = true;
            }
            acc += ntl;
        }
        if (!live) return;                 // uniform exit for dead tiles

        // fill this tile's token list
#pragma unroll
        for (int i = 0; i < 4; i++) {
            int G    = i * 8 + wid;
            int t    = G * 32 + lane;
            int rank = pre[G * P_ + rr[i]] + rkg[i];
            int lr   = rank - lrow0;
            if (rr[i] == p && (unsigned)lr < (unsigned)BM) toks[lr] = t;
        }
        {   // 256 threads: one bias element each (4 gates x 64 cols)
            int j = tid >> 6, c = tid & 63;
            bias_sm[tid] = bs_l[((size_t)j * P_ + p) * D_ + n0 + c];
        }
        __syncthreads();
        if (tid >= nrows && tid < BM) toks[tid] = toks[nrows - 1];   // pad dummy rows
        __syncthreads();

        // -- GEMM body --
        const uint32_t sb = smem_u32(dsm);

        // ---- per-thread staging setup ----
        const float* bsrc[4];
        uint32_t     bsts[4];
#pragma unroll
        for (int i = 0; i < 4; i++) {
            int idx = tid + i * NTH;
            int k = idx >> 5, nc = idx & 31;
            int j = nc >> 3, col = (nc & 7) * 8;
            bsrc[i] = Ws_l + ((size_t)j * P_ + p) * (size_t)(D_ * D_) + (size_t)k * D_ + n0 + col;
            bsts[i] = (uint32_t)(k * B_STRIDE + nc * 16);
        }
        const float* asrc = nullptr;
        uint32_t     asts = 0;
        if (tid < 192) {
            int m = tid >> 2, kq = tid & 3;
            asrc = x_in + (size_t)toks[m] * D_ + kq * 8;
            asts = (uint32_t)(m * A_STRIDE + kq * 16);
        }

        // prefetch chunk 0
        float4 br[4][2];
        float4 ar[2];
#pragma unroll
        for (int i = 0; i < 4; i++) {
            br[i][0] = *reinterpret_cast<const float4*>(bsrc[i]);
            br[i][1] = *reinterpret_cast<const float4*>(bsrc[i] + 4);
        }
        if (tid < 192) {
            ar[0] = *reinterpret_cast<const float4*>(asrc);
            ar[1] = *reinterpret_cast<const float4*>(asrc + 4);
        }

        const int j_w    = wid >> 1;
        const int nhalf  = (wid & 1) * 32;
        const int ncbase = (j_w * 64 + nhalf) >> 3;

        const int a_row  = lane & 15;
        const int a_koff = lane >> 4;
        const int b_krow = (lane & 7) + ((lane >> 3) & 1) * 8;
        const int b_noff = lane >> 4;

        float acc_f[3][4][4];
#pragma unroll
        for (int mf = 0; mf < 3; mf++)
#pragma unroll
            for (int nf = 0; nf < 4; nf++)
#pragma unroll
                for (int q = 0; q < 4; q++) acc_f[mf][nf][q] = 0.f;

        for (int s = 0; s < NCH; s++) {
            const uint32_t aoff = (s & 1) ? OFF_A1 : OFF_A0;
            const uint32_t boff = (s & 1) ? OFF_B1 : OFF_B0;
            const uint32_t ab = sb + aoff;
            const uint32_t bb = sb + boff;

            // ---- STS staged regs (fp32 -> fp16 pack) ----
#pragma unroll
            for (int i = 0; i < 4; i++) {
                uint4 v;
                v.x = pk2(br[i][0].x, br[i][0].y);
                v.y = pk2(br[i][0].z, br[i][0].w);
                v.z = pk2(br[i][1].x, br[i][1].y);
                v.w = pk2(br[i][1].z, br[i][1].w);
                *reinterpret_cast<uint4*>(dsm + boff + bsts[i]) = v;
            }
            if (tid < 192) {
                uint4 v;
                v.x = pk2(ar[0].x, ar[0].y);
                v.y = pk2(ar[0].z, ar[0].w);
                v.z = pk2(ar[1].x, ar[1].y);
                v.w = pk2(ar[1].z, ar[1].w);
                *reinterpret_cast<uint4*>(dsm + aoff + asts) = v;
            }
            __syncthreads();

            // ---- prefetch next chunk into registers (R6 position) ----
            if (s + 1 < NCH) {
#pragma unroll
                for (int i = 0; i < 4; i++) {
                    bsrc[i] += KC * D_;
                    br[i][0] = *reinterpret_cast<const float4*>(bsrc[i]);
                    br[i][1] = *reinterpret_cast<const float4*>(bsrc[i] + 4);
                }
                if (tid < 192) {
                    asrc += KC;
                    ar[0] = *reinterpret_cast<const float4*>(asrc);
                    ar[1] = *reinterpret_cast<const float4*>(asrc + 4);
                }
            }
            // ---- L2 prefetch of chunk s+2 B data (hint only) ----
            if (s + 2 < NCH) {
#pragma unroll
                for (int i = 0; i < 4; i++)
                    asm volatile("prefetch.global.L2 [%0];" :: "l"(bsrc[i] + KC * D_));
            }

            // ---- compute: 2 k16 steps ----
#pragma unroll
            for (int ks = 0; ks < 2; ks++) {
                uint32_t afr[3][4];
#pragma unroll
                for (int mf = 0; mf < 3; mf++) {
                    uint32_t addr = ab + (uint32_t)((mf * 16 + a_row) * A_STRIDE
                                                    + (ks * 2 + a_koff) * 16);
                    ldsm_x4(afr[mf], addr);
                }
                uint32_t bfr[2][4];
#pragma unroll
                for (int nf2 = 0; nf2 < 2; nf2++) {
                    uint32_t addr = bb + (uint32_t)((ks * 16 + b_krow) * B_STRIDE
                                                    + (ncbase + nf2 * 2 + b_noff) * 16);
                    ldsm_x4_t(bfr[nf2], addr);
                }
#pragma unroll
                for (int mf = 0; mf < 3; mf++)
#pragma unroll
                    for (int nf = 0; nf < 4; nf++) {
                        int nf2 = nf >> 1, sel = (nf & 1) * 2;
                        mma16816(acc_f[mf][nf], afr[mf], bfr[nf2][sel], bfr[nf2][sel + 1]);
                    }
            }
        }

        // ---- epilogue: exchange gate accumulators through smem, fuse gating ----
        __syncthreads();
        float* epi = reinterpret_cast<float*>(dsm + SM_STAGE);     // [4][BM][EPI_STRIDE]

#pragma unroll
        for (int mf = 0; mf < 3; mf++)
#pragma unroll
            for (int nf = 0; nf < 4; nf++) {
                int r = mf * 16 + (lane >> 2);
                int c = nhalf + nf * 8 + (lane & 3) * 2;
                float* e0 = epi + ((j_w * BM + r) * EPI_STRIDE + c);
                e0[0] = acc_f[mf][nf][0];
                e0[1] = acc_f[mf][nf][1];
                float* e1 = epi + ((j_w * BM + r + 8) * EPI_STRIDE + c);
                e1[0] = acc_f[mf][nf][2];
                e1[1] = acc_f[mf][nf][3];
            }
        __syncthreads();

#pragma unroll
        for (int i = 0; i < (BM * 64) / NTH; i++) {     // 12 iterations
            int flat = tid + i * NTH;          // 0..3071 = 48m x 64c
            int m = flat >> 6, c = flat & 63;
            if (m < nrows) {
                int tok = toks[m];
                float sf = epi[(0 * BM + m) * EPI_STRIDE + c] + bias_sm[0 * 64 + c];
                float lg = epi[(1 * BM + m) * EPI_STRIDE + c] + bias_sm[1 * 64 + c];
                float lf = epi[(2 * BM + m) * EPI_STRIDE + c] + bias_sm[2 * 64 + c];
                float of = epi[(3 * BM + m) * EPI_STRIDE + c] + bias_sm[3 * 64 + c];
                float xv = x_in[(size_t)tok * D_ + n0 + c];
                float nr = xv * sigm_f(sf) + tanh_f(lg) * sigm_f(lf);
                x_out[(size_t)tok * D_ + n0 + c] = tanh_f(nr) * sigm_f(of);
            }
        }
    }
}

// ---------------- launch ----------------
extern "C" void kernel_launch(void* const* d_in, const int* in_sizes, int n_in,
                              void* d_out, int out_size)
{
    const int*   positions = nullptr;
    const float* x0 = nullptr;
    const float* Ws = nullptr;
    const float* bs = nullptr;
    for (int i = 0; i < n_in; i++) {
        switch (in_sizes[i]) {
            case NT:                    positions = (const int*)d_in[i];   break;
            case NT * D_:               x0        = (const float*)d_in[i]; break;
            case L_ * 4 * P_ * D_ * D_: Ws        = (const float*)d_in[i]; break;
            case L_ * 4 * P_ * D_:      bs        = (const float*)d_in[i]; break;
            default: break;
        }
    }
    float* out = (float*)d_out;

    cudaFuncSetAttribute(layer_kernel,
                         cudaFuncAttributeMaxDynamicSharedMemorySize, SMEM_TOTAL);

    const size_t W_layer = (size_t)4 * P_ * D_ * D_;
    const size_t b_layer = (size_t)4 * P_ * D_;

    dim3 grid(MAX_TILES, D_ / BN);      // 40 x 8 (real tiles ~27 -> ~216 live CTAs)

    // Layer 0: x0 -> g_mid
    layer_kernel<<<grid, NTH, SMEM_TOTAL>>>(positions, x0, out, Ws, bs, 0, 1);
    // Layer 1: g_mid -> d_out
    layer_kernel<<<grid, NTH, SMEM_TOTAL>>>(positions, x0, out,
                                            Ws + W_layer, bs + b_layer, 1, 0);

    (void)out_size;
}

// round 13
// speedup vs baseline: 1.3167x; 1.3167x over previous
#include <cuda_runtime.h>
#include <cuda_fp16.h>
#include <cstdint>

// ---------------- problem constants ----------------
#define NT   1024          // T*B tokens
#define D_   512
#define L_   2
#define P_   17            // MULTI_INFER_NUM + 1

// ---------------- tiling ----------------
#define BM        48       // tokens per m-tile (3 x m16)
#define BN        32       // output cols per gate per CTA (x4 gates = 128 N)
#define KC        32       // k chunk per stage
#define NCH       (D_/KC)  // 16 chunks
#define MAX_TILES 40       // sum ceil(cnt_p/48) <= 17 + 21 = 38
#define NTH       256      // 8 warps

// smem byte strides (padded, conflict-free ldmatrix without XOR swizzle)
#define A_STRIDE  80       // 32 halfs (64B) padded to 80B per m-row
#define B_STRIDE  272      // 128 halfs (256B) padded to 272B per k-row
#define ASZ       (BM * A_STRIDE)     // 3840
#define BSZ       (KC * B_STRIDE)     // 8704

// dynamic smem layout
#define SM_TOKS   0                   // 48 * 4 = 192
#define SM_BIAS   192                 // 4*32*4 = 512 -> ends 704
#define SM_STAGE  768                 // stage buffers / epilogue union
#define OFF_A0    (SM_STAGE)
#define OFF_A1    (SM_STAGE + ASZ)
#define OFF_B0    (SM_STAGE + 2*ASZ)
#define OFF_B1    (SM_STAGE + 2*ASZ + BSZ)
#define EPI_STRIDE 33                 // fp32 cols incl. pad
#define EPI_BYTES (4 * BM * EPI_STRIDE * 4)        // 25344
#define STAGE_END (SM_STAGE + 2*ASZ + 2*BSZ)       // 25856
#define SMEM_TOTAL ((SM_STAGE + EPI_BYTES) > STAGE_END ? (SM_STAGE + EPI_BYTES) : STAGE_END)

// ---------------- device scratch ----------------
__device__ int   g_token_idx[NT];
__device__ int   g_tile_bucket[MAX_TILES];
__device__ int   g_tile_row[MAX_TILES];
__device__ int   g_tile_nrows[MAX_TILES];
__device__ int   g_num_tiles;
__device__ float g_mid[NT * D_];     // layer-0 output ping buffer (2 MB)

// ---------------- helpers ----------------
__device__ __forceinline__ uint32_t smem_u32(const void* p) {
    uint32_t a;
    asm("{ .reg .u64 t; cvta.to.shared.u64 t, %1; cvt.u32.u64 %0, t; }" : "=r"(a) : "l"(p));
    return a;
}
__device__ __forceinline__ uint32_t pk2(float a, float b) {
    __half2 h = __floats2half2_rn(a, b);
    return *reinterpret_cast<uint32_t*>(&h);
}
__device__ __forceinline__ void ldsm_x4(uint32_t* r, uint32_t addr) {
    asm volatile("ldmatrix.sync.aligned.m8n8.x4.shared.b16 {%0,%1,%2,%3}, [%4];"
                 : "=r"(r[0]), "=r"(r[1]), "=r"(r[2]), "=r"(r[3]) : "r"(addr));
}
__device__ __forceinline__ void ldsm_x4_t(uint32_t* r, uint32_t addr) {
    asm volatile("ldmatrix.sync.aligned.m8n8.x4.trans.shared.b16 {%0,%1,%2,%3}, [%4];"
                 : "=r"(r[0]), "=r"(r[1]), "=r"(r[2]), "=r"(r[3]) : "r"(addr));
}
__device__ __forceinline__ void mma16816(float* c, const uint32_t* a, uint32_t b0, uint32_t b1) {
    asm volatile(
        "mma.sync.aligned.m16n8k16.row.col.f32.f16.f16.f32 "
        "{%0,%1,%2,%3}, {%4,%5,%6,%7}, {%8,%9}, {%0,%1,%2,%3};"
        : "+f"(c[0]), "+f"(c[1]), "+f"(c[2]), "+f"(c[3])
        : "r"(a[0]), "r"(a[1]), "r"(a[2]), "r"(a[3]), "r"(b0), "r"(b1));
}
__device__ __forceinline__ float sigm_f(float v) { return 1.f / (1.f + __expf(-v)); }
__device__ __forceinline__ float tanh_f(float v) { return 2.f / (1.f + __expf(-2.f * v)) - 1.f; }

// ---------------- bucket list construction ----------------
__global__ void build_lists_kernel(const int* __restrict__ positions) {
    __shared__ int cnt[P_];
    __shared__ int off[P_ + 1];
    const int tid = threadIdx.x;          // one thread per token
    if (tid < P_) cnt[tid] = 0;
    __syncthreads();
    int r = positions[tid];
    r = (r < 16) ? r : 16;
    int rank = atomicAdd(&cnt[r], 1);
    __syncthreads();
    if (tid == 0) {
        int s = 0;
        for (int p = 0; p < P_; p++) { off[p] = s; s += cnt[p]; }
        off[P_] = s;
        int nt = 0;
        for (int p = 0; p < P_; p++) {
            for (int row = 0; row < cnt[p]; row += BM) {
                g_tile_bucket[nt] = p;
                g_tile_row[nt]    = off[p] + row;
                int rem = cnt[p] - row;
                g_tile_nrows[nt]  = rem < BM ? rem : BM;
                nt++;
            }
        }
        g_num_tiles = nt;
    }
    __syncthreads();
    g_token_idx[off[r] + rank] = tid;
}

// ---------------- fused per-layer HMMA GEMM + gating ----------------
__global__ void __launch_bounds__(NTH, 3)
layer_kernel(const float* __restrict__ x_ext_in,
             float* __restrict__ x_ext_out,
             const float* __restrict__ Ws_l,   // [4][P][D][D] fp32 for this layer
             const float* __restrict__ bs_l,   // [4][P][D]
             int in_is_mid, int out_is_mid)
{
    extern __shared__ __align__(16) char dsm[];
    int*   toks    = reinterpret_cast<int*>(dsm + SM_TOKS);
    float* bias_sm = reinterpret_cast<float*>(dsm + SM_BIAS);

    const float* x_in  = in_is_mid  ? g_mid : x_ext_in;
    float*       x_out = out_is_mid ? g_mid : x_ext_out;

    const int tile = blockIdx.x;
    if (tile >= g_num_tiles) return;
    const int p     = g_tile_bucket[tile];
    const int row0  = g_tile_row[tile];
    const int nrows = g_tile_nrows[tile];
    const int n0    = blockIdx.y * BN;

    const int tid  = threadIdx.x;
    const int wid  = tid >> 5;
    const int lane = tid & 31;

    if (tid < BM) {
        int mm = (tid < nrows) ? tid : (nrows - 1);
        toks[tid] = g_token_idx[row0 + mm];
    }
    if (tid < 128) {   // one bias element each (4 gates x 32 cols)
        int j = tid >> 5, c = tid & 31;
        bias_sm[tid] = bs_l[((size_t)j * P_ + p) * D_ + n0 + c];
    }
    __syncthreads();

    const uint32_t sb = smem_u32(dsm);

    // ---- per-thread staging setup ----
    // B: 2 units/thread over 512 units: k=idx>>4, nc=idx&15; gate j=nc>>2, col=(nc&3)*8
    const float* bsrc[2];
    uint32_t     bsts[2];
#pragma unroll
    for (int i = 0; i < 2; i++) {
        int idx = tid + i * NTH;
        int k = idx >> 4, nc = idx & 15;
        int j = nc >> 2, col = (nc & 3) * 8;
        bsrc[i] = Ws_l + ((size_t)j * P_ + p) * (size_t)(D_ * D_) + (size_t)k * D_ + n0 + col;
        bsts[i] = (uint32_t)(k * B_STRIDE + nc * 16);
    }
    // A: threads 0..191: m = tid>>2, kq = tid&3 (8 floats each; 48*32 = 1536 fp32)
    const float* asrc = nullptr;
    uint32_t     asts = 0;
    if (tid < 192) {
        int m = tid >> 2, kq = tid & 3;
        asrc = x_in + (size_t)toks[m] * D_ + kq * 8;
        asts = (uint32_t)(m * A_STRIDE + kq * 16);
    }

    // prefetch chunk 0
    float4 br[2][2];
    float4 ar[2];
#pragma unroll
    for (int i = 0; i < 2; i++) {
        br[i][0] = *reinterpret_cast<const float4*>(bsrc[i]);
        br[i][1] = *reinterpret_cast<const float4*>(bsrc[i] + 4);
    }
    if (tid < 192) {
        ar[0] = *reinterpret_cast<const float4*>(asrc);
        ar[1] = *reinterpret_cast<const float4*>(asrc + 4);
    }

    // warp tile: gate j_w (4), 16-col half within the 32-col slice
    const int j_w    = wid >> 1;
    const int nhalf  = (wid & 1) * 16;
    const int ncbase = j_w * 4 + (wid & 1) * 2;     // 16B-chunk base within B rows

    const int a_row  = lane & 15;
    const int a_koff = lane >> 4;
    const int b_krow = (lane & 7) + ((lane >> 3) & 1) * 8;
    const int b_noff = lane >> 4;

    float acc[3][2][4];
#pragma unroll
    for (int mf = 0; mf < 3; mf++)
#pragma unroll
        for (int nf = 0; nf < 2; nf++)
#pragma unroll
            for (int q = 0; q < 4; q++) acc[mf][nf][q] = 0.f;

    for (int s = 0; s < NCH; s++) {
        const uint32_t aoff = (s & 1) ? OFF_A1 : OFF_A0;
        const uint32_t boff = (s & 1) ? OFF_B1 : OFF_B0;
        const uint32_t ab = sb + aoff;
        const uint32_t bb = sb + boff;

        // ---- STS staged regs (fp32 -> fp16 pack) ----
#pragma unroll
        for (int i = 0; i < 2; i++) {
            uint4 v;
            v.x = pk2(br[i][0].x, br[i][0].y);
            v.y = pk2(br[i][0].z, br[i][0].w);
            v.z = pk2(br[i][1].x, br[i][1].y);
            v.w = pk2(br[i][1].z, br[i][1].w);
            *reinterpret_cast<uint4*>(dsm + boff + bsts[i]) = v;
        }
        if (tid < 192) {
            uint4 v;
            v.x = pk2(ar[0].x, ar[0].y);
            v.y = pk2(ar[0].z, ar[0].w);
            v.z = pk2(ar[1].x, ar[1].y);
            v.w = pk2(ar[1].z, ar[1].w);
            *reinterpret_cast<uint4*>(dsm + aoff + asts) = v;
        }
        __syncthreads();

        // ---- prefetch next chunk into registers (R6 position) ----
        if (s + 1 < NCH) {
#pragma unroll
            for (int i = 0; i < 2; i++) {
                bsrc[i] += KC * D_;
                br[i][0] = *reinterpret_cast<const float4*>(bsrc[i]);
                br[i][1] = *reinterpret_cast<const float4*>(bsrc[i] + 4);
            }
            if (tid < 192) {
                asrc += KC;
                ar[0] = *reinterpret_cast<const float4*>(asrc);
                ar[1] = *reinterpret_cast<const float4*>(asrc + 4);
            }
        }

        // ---- compute: 2 k16 steps ----
#pragma unroll
        for (int ks = 0; ks < 2; ks++) {
            uint32_t afr[3][4];
#pragma unroll
            for (int mf = 0; mf < 3; mf++) {
                uint32_t addr = ab + (uint32_t)((mf * 16 + a_row) * A_STRIDE
                                                + (ks * 2 + a_koff) * 16);
                ldsm_x4(afr[mf], addr);
            }
            uint32_t bfr[4];
            {
                uint32_t addr = bb + (uint32_t)((ks * 16 + b_krow) * B_STRIDE
                                                + (ncbase + b_noff) * 16);
                ldsm_x4_t(bfr, addr);
            }
#pragma unroll
            for (int mf = 0; mf < 3; mf++)
#pragma unroll
                for (int nf = 0; nf < 2; nf++) {
                    int sel = nf * 2;
                    mma16816(acc[mf][nf], afr[mf], bfr[sel], bfr[sel + 1]);
                }
        }
    }

    // ---- epilogue: exchange gate accumulators through smem, fuse gating ----
    __syncthreads();                       // stage buffers free -> reuse as epi
    float* epi = reinterpret_cast<float*>(dsm + SM_STAGE);     // [4][BM][EPI_STRIDE]

#pragma unroll
    for (int mf = 0; mf < 3; mf++)
#pragma unroll
        for (int nf = 0; nf < 2; nf++) {
            int r = mf * 16 + (lane >> 2);
            int c = nhalf + nf * 8 + (lane & 3) * 2;
            float* e0 = epi + ((j_w * BM + r) * EPI_STRIDE + c);
            e0[0] = acc[mf][nf][0];
            e0[1] = acc[mf][nf][1];
            float* e1 = epi + ((j_w * BM + r + 8) * EPI_STRIDE + c);
            e1[0] = acc[mf][nf][2];
            e1[1] = acc[mf][nf][3];
        }
    __syncthreads();

#pragma unroll
    for (int i = 0; i < (BM * 32) / NTH; i++) {     // 6 iterations
        int flat = tid + i * NTH;          // 0..1535 = 48m x 32c
        int m = flat >> 5, c = flat & 31;
        if (m < nrows) {
            int tok = toks[m];
            float sf = epi[(0 * BM + m) * EPI_STRIDE + c] + bias_sm[0 * 32 + c];
            float lg = epi[(1 * BM + m) * EPI_STRIDE + c] + bias_sm[1 * 32 + c];
            float lf = epi[(2 * BM + m) * EPI_STRIDE + c] + bias_sm[2 * 32 + c];
            float of = epi[(3 * BM + m) * EPI_STRIDE + c] + bias_sm[3 * 32 + c];
            float xv = x_in[(size_t)tok * D_ + n0 + c];
            float nr = xv * sigm_f(sf) + tanh_f(lg) * sigm_f(lf);
            x_out[(size_t)tok * D_ + n0 + c] = tanh_f(nr) * sigm_f(of);
        }
    }
}

// ---------------- launch ----------------
extern "C" void kernel_launch(void* const* d_in, const int* in_sizes, int n_in,
                              void* d_out, int out_size)
{
    const int*   positions = nullptr;
    const float* x0 = nullptr;
    const float* Ws = nullptr;
    const float* bs = nullptr;
    for (int i = 0; i < n_in; i++) {
        switch (in_sizes[i]) {
            case NT:                    positions = (const int*)d_in[i];   break;
            case NT * D_:               x0        = (const float*)d_in[i]; break;
            case L_ * 4 * P_ * D_ * D_: Ws        = (const float*)d_in[i]; break;
            case L_ * 4 * P_ * D_:      bs        = (const float*)d_in[i]; break;
            default: break;
        }
    }
    float* out = (float*)d_out;

    cudaFuncSetAttribute(layer_kernel,
                         cudaFuncAttributeMaxDynamicSharedMemorySize, SMEM_TOTAL);

    const size_t W_layer = (size_t)4 * P_ * D_ * D_;
    const size_t b_layer = (size_t)4 * P_ * D_;

    build_lists_kernel<<<1, NT>>>(positions);

    dim3 grid(MAX_TILES, D_ / BN);      // 40 x 16 (live ~27x16 = 432 CTAs, 3/SM)

    // Layer 0: x0 -> g_mid
    layer_kernel<<<grid, NTH, SMEM_TOTAL>>>(x0, out, Ws, bs, 0, 1);
    // Layer 1: g_mid -> d_out
    layer_kernel<<<grid, NTH, SMEM_TOTAL>>>(x0, out, Ws + W_layer, bs + b_layer, 1, 0);

    (void)out_size;
}